// round 1
// baseline (speedup 1.0000x reference)
#include <cuda_runtime.h>
#include <cstddef>

// Problem constants
#define BB 8
#define TT 2048
#define DD 1024
#define HH 8
#define NN 32
#define MROWS (BB*TT)          // 16384
#define HN (HH*NN)             // 256

// ---------------------------------------------------------------------------
// Scratch (no cudaMalloc allowed) — __device__ globals.
// ---------------------------------------------------------------------------
__device__ float g_xp  [(size_t)MROWS * DD];   // 64 MB
__device__ float g_k   [(size_t)MROWS * HN];   // 16 MB
__device__ float g_v   [(size_t)MROWS * HN];
__device__ float g_q   [(size_t)MROWS * HN];
__device__ float g_beta[(size_t)MROWS * HN];
__device__ float g_cell[(size_t)MROWS * HN];

// ---------------------------------------------------------------------------
// GEMM: C[M,Nout] = epi( A[M,K] @ W[Nout,K]^T )   (all row-major, fp32)
// EPI: 0 = identity, 1 = silu, 2 = sigmoid(acc + bias[col])
// 128x128 tile, BK=8, 256 threads, 8x8 per-thread micro-tile.
// Requires M%128==0, Nout%128==0, K%8==0 (true for all our shapes).
// ---------------------------------------------------------------------------
#define BM 128
#define BN 128
#define BK 8
#define TM 8
#define TN 8

template<int EPI>
__global__ void __launch_bounds__(256)
gemm_awt(const float* __restrict__ A, const float* __restrict__ W,
         float* __restrict__ C, const float* __restrict__ bias,
         int M, int Nout, int K)
{
    __shared__ float As[BK][BM];
    __shared__ float Bs[BK][BN];

    const int tid  = threadIdx.x;
    const int row0 = blockIdx.y * BM;
    const int col0 = blockIdx.x * BN;

    // load mapping: 128 rows x 8 K-cols per tile, float4 along K
    const int lr = tid >> 1;            // 0..127
    const int lc = (tid & 1) << 2;      // 0 or 4

    const float* Ap = A + (size_t)(row0 + lr) * K + lc;
    const float* Wp = W + (size_t)(col0 + lr) * K + lc;

    const int ty = (tid >> 4) * TM;     // 0..120
    const int tx = (tid & 15) * TN;     // 0..120

    float acc[TM][TN];
#pragma unroll
    for (int m = 0; m < TM; ++m)
#pragma unroll
        for (int n = 0; n < TN; ++n) acc[m][n] = 0.f;

    for (int k0 = 0; k0 < K; k0 += BK) {
        float4 av = *reinterpret_cast<const float4*>(Ap + k0);
        float4 wv = *reinterpret_cast<const float4*>(Wp + k0);
        As[lc + 0][lr] = av.x; As[lc + 1][lr] = av.y;
        As[lc + 2][lr] = av.z; As[lc + 3][lr] = av.w;
        Bs[lc + 0][lr] = wv.x; Bs[lc + 1][lr] = wv.y;
        Bs[lc + 2][lr] = wv.z; Bs[lc + 3][lr] = wv.w;
        __syncthreads();

#pragma unroll
        for (int kk = 0; kk < BK; ++kk) {
            float a[TM], bvr[TN];
#pragma unroll
            for (int m = 0; m < TM; ++m) a[m] = As[kk][ty + m];
#pragma unroll
            for (int n = 0; n < TN; ++n) bvr[n] = Bs[kk][tx + n];
#pragma unroll
            for (int m = 0; m < TM; ++m)
#pragma unroll
                for (int n = 0; n < TN; ++n)
                    acc[m][n] = fmaf(a[m], bvr[n], acc[m][n]);
        }
        __syncthreads();
    }

#pragma unroll
    for (int m = 0; m < TM; ++m) {
        float* crow = C + (size_t)(row0 + ty + m) * Nout + col0 + tx;
#pragma unroll
        for (int n = 0; n < TN; ++n) {
            float v = acc[m][n];
            if (EPI == 1) {                       // silu
                v = v / (1.f + expf(-v));
            } else if (EPI == 2) {                // sigmoid(acc + bias)
                v = 1.f / (1.f + expf(-(v + bias[col0 + tx + n])));
            }
            crow[n] = v;
        }
    }
}

// ---------------------------------------------------------------------------
// Sequential scan. One block per (b,h) chain. 1024 threads: warp = state row i,
// lane = state col j. State S[i][j] lives in one register per thread.
// ---------------------------------------------------------------------------
__device__ __forceinline__ float warp_sum(float v) {
#pragma unroll
    for (int o = 16; o > 0; o >>= 1) v += __shfl_xor_sync(0xffffffffu, v, o);
    return v;
}

__global__ void __launch_bounds__(1024)
scan_kernel(const float* __restrict__ Kp, const float* __restrict__ Vp,
            const float* __restrict__ Qp, const float* __restrict__ Bp,
            float* __restrict__ cell, float* __restrict__ S_final, int writeS)
{
    const int bh = blockIdx.x;            // 0..63
    const int b  = bh >> 3;               // /H
    const int h  = bh & 7;                // %H
    const int tid = threadIdx.x;
    const int i = tid >> 5;               // warp id = row
    const int j = tid & 31;               // lane  = col

    __shared__ float sk[NN], sv[NN], sq[NN], sb[NN], skn[NN];

    float S = 0.f;
    size_t base = ((size_t)b * TT) * HN + (size_t)h * NN;

    for (int t = 0; t < TT; ++t, base += HN) {
        if (tid < 32)       sk[tid]      = Kp[base + tid];
        else if (tid < 64)  sv[tid - 32] = Vp[base + tid - 32];
        else if (tid < 96)  sq[tid - 64] = Qp[base + tid - 64];
        else if (tid < 128) sb[tid - 96] = Bp[base + tid - 96];
        __syncthreads();

        if (tid < 32) {
            float kv = sk[tid];
            float s2 = warp_sum(kv * kv);
            skn[tid] = kv / (sqrtf(s2) + 1e-6f);
        }
        __syncthreads();

        const float knj = skn[j];
        // retrieved_i = sum_j S_ij * kn_j
        const float r = warp_sum(S * knj);
        const float delta_i = sv[i] - r;
        // state update
        S = tanhf(sb[i] * S + delta_i * knj);
        // Sq_i = sum_j S_ij * q_j
        const float sqi = warp_sum(S * sq[j]);
        if (j == 0) {
            // out = Sq * silu(Sq) = Sq^2 * sigmoid(Sq)
            cell[base + i] = sqi * sqi / (1.f + expf(-sqi));
        }
        __syncthreads();   // protect shared arrays before next step's loads
    }

    if (writeS) {
        S_final[((size_t)bh * NN + i) * NN + j] = S;
    }
}

// ---------------------------------------------------------------------------
// Host launcher
// ---------------------------------------------------------------------------
extern "C" void kernel_launch(void* const* d_in, const int* in_sizes, int n_in,
                              void* d_out, int out_size)
{
    const float* x      = (const float*)d_in[0];
    const float* W_in   = (const float*)d_in[1];
    const float* W_k    = (const float*)d_in[2];
    const float* W_v    = (const float*)d_in[3];
    const float* W_q    = (const float*)d_in[4];
    const float* W_beta = (const float*)d_in[5];
    const float* b_beta = (const float*)d_in[6];
    const float* W_out  = (const float*)d_in[7];
    float* y = (float*)d_out;

    float *xp, *k, *v, *q, *bt, *cell;
    cudaGetSymbolAddress((void**)&xp,   g_xp);
    cudaGetSymbolAddress((void**)&k,    g_k);
    cudaGetSymbolAddress((void**)&v,    g_v);
    cudaGetSymbolAddress((void**)&q,    g_q);
    cudaGetSymbolAddress((void**)&bt,   g_beta);
    cudaGetSymbolAddress((void**)&cell, g_cell);

    const int M = MROWS;

    // 1. xp = silu(x @ W_in^T)           [16384,1024] x [1024,1024]
    gemm_awt<1><<<dim3(DD / BN, M / BM), 256>>>(x, W_in, xp, nullptr, M, DD, DD);

    // 2-5. projections                    [16384,256] = xp @ W^T
    gemm_awt<0><<<dim3(HN / BN, M / BM), 256>>>(xp, W_k,    k,  nullptr, M, HN, DD);
    gemm_awt<0><<<dim3(HN / BN, M / BM), 256>>>(xp, W_v,    v,  nullptr, M, HN, DD);
    gemm_awt<0><<<dim3(HN / BN, M / BM), 256>>>(xp, W_q,    q,  nullptr, M, HN, DD);
    gemm_awt<2><<<dim3(HN / BN, M / BM), 256>>>(xp, W_beta, bt, b_beta,  M, HN, DD);

    // 6. sequential scan over T
    const size_t y_elems = (size_t)M * DD;
    const int writeS = (out_size >= (int)(y_elems + (size_t)BB * HH * NN * NN)) ? 1 : 0;
    scan_kernel<<<BB * HH, 1024>>>(k, v, q, bt, cell, y + y_elems, writeS);

    // 7. y = cell @ W_out^T               [16384,1024] = [16384,256] x [1024,256]^T
    gemm_awt<0><<<dim3(DD / BN, M / BM), 256>>>(cell, W_out, y, nullptr, M, DD, HN);
}

// round 2
// speedup vs baseline: 1.3964x; 1.3964x over previous
#include <cuda_runtime.h>
#include <cstddef>

// Problem constants
#define BB 8
#define TT 2048
#define DD 1024
#define HH 8
#define NN 32
#define MROWS (BB*TT)          // 16384
#define HN (HH*NN)             // 256

// ---------------------------------------------------------------------------
// Scratch (no cudaMalloc allowed) — __device__ globals.
// ---------------------------------------------------------------------------
__device__ float g_xp  [(size_t)MROWS * DD];   // 64 MB
__device__ float g_k   [(size_t)MROWS * HN];   // 16 MB
__device__ float g_v   [(size_t)MROWS * HN];
__device__ float g_q   [(size_t)MROWS * HN];
__device__ float g_beta[(size_t)MROWS * HN];
__device__ float g_cell[(size_t)MROWS * HN];

// ---------------------------------------------------------------------------
// Shared double-buffered SGEMM core.
// C[M,Nout] = epi( A[M,K] @ W[Nout,K]^T )   row-major fp32
// epi: 0 identity, 1 silu, 2 sigmoid(acc + bias[col])
// 128x128 tile, BK=8, 256 threads, 8x8 micro-tile, double-buffered smem.
// ---------------------------------------------------------------------------
#define BM 128
#define BN 128
#define BK 8
#define TM 8
#define TN 8

__device__ __forceinline__ void gemm_core(
    const float* __restrict__ A, const float* __restrict__ W,
    float* __restrict__ C, const float* __restrict__ bias,
    int epi, int Nout, int K, int row0, int col0)
{
    __shared__ float As[2][BK][BM];
    __shared__ float Bs[2][BK][BN];

    const int tid = threadIdx.x;
    const int lr = tid >> 1;            // 0..127
    const int lc = (tid & 1) << 2;      // 0 or 4

    const float* Ap = A + (size_t)(row0 + lr) * K + lc;
    const float* Wp = W + (size_t)(col0 + lr) * K + lc;

    const int ty = (tid >> 4) * TM;     // 0..120
    const int tx = (tid & 15) * TN;     // 0..120

    float acc[TM][TN];
#pragma unroll
    for (int m = 0; m < TM; ++m)
#pragma unroll
        for (int n = 0; n < TN; ++n) acc[m][n] = 0.f;

    const int ntiles = K / BK;

    float4 av = *reinterpret_cast<const float4*>(Ap);
    float4 wv = *reinterpret_cast<const float4*>(Wp);
    As[0][lc + 0][lr] = av.x; As[0][lc + 1][lr] = av.y;
    As[0][lc + 2][lr] = av.z; As[0][lc + 3][lr] = av.w;
    Bs[0][lc + 0][lr] = wv.x; Bs[0][lc + 1][lr] = wv.y;
    Bs[0][lc + 2][lr] = wv.z; Bs[0][lc + 3][lr] = wv.w;
    __syncthreads();

    for (int kt = 0; kt < ntiles; ++kt) {
        const int cur = kt & 1;
        if (kt + 1 < ntiles) {
            av = *reinterpret_cast<const float4*>(Ap + (size_t)(kt + 1) * BK);
            wv = *reinterpret_cast<const float4*>(Wp + (size_t)(kt + 1) * BK);
        }
#pragma unroll
        for (int kk = 0; kk < BK; ++kk) {
            float4 a0 = *reinterpret_cast<const float4*>(&As[cur][kk][ty]);
            float4 a1 = *reinterpret_cast<const float4*>(&As[cur][kk][ty + 4]);
            float4 b0 = *reinterpret_cast<const float4*>(&Bs[cur][kk][tx]);
            float4 b1 = *reinterpret_cast<const float4*>(&Bs[cur][kk][tx + 4]);
            float a[TM] = {a0.x, a0.y, a0.z, a0.w, a1.x, a1.y, a1.z, a1.w};
            float bb[TN] = {b0.x, b0.y, b0.z, b0.w, b1.x, b1.y, b1.z, b1.w};
#pragma unroll
            for (int m = 0; m < TM; ++m)
#pragma unroll
                for (int n = 0; n < TN; ++n)
                    acc[m][n] = fmaf(a[m], bb[n], acc[m][n]);
        }
        if (kt + 1 < ntiles) {
            const int nxt = cur ^ 1;
            As[nxt][lc + 0][lr] = av.x; As[nxt][lc + 1][lr] = av.y;
            As[nxt][lc + 2][lr] = av.z; As[nxt][lc + 3][lr] = av.w;
            Bs[nxt][lc + 0][lr] = wv.x; Bs[nxt][lc + 1][lr] = wv.y;
            Bs[nxt][lc + 2][lr] = wv.z; Bs[nxt][lc + 3][lr] = wv.w;
            __syncthreads();
        }
    }

#pragma unroll
    for (int m = 0; m < TM; ++m) {
        float* crow = C + (size_t)(row0 + ty + m) * Nout + col0 + tx;
#pragma unroll
        for (int n = 0; n < TN; ++n) {
            float v = acc[m][n];
            if (epi == 1) {
                v = v / (1.f + expf(-v));                       // silu
            } else if (epi == 2) {
                v = 1.f / (1.f + expf(-(v + bias[col0 + tx + n])));  // sigmoid+bias
            }
            crow[n] = v;
        }
    }
}

template<int EPI>
__global__ void __launch_bounds__(256, 2)
gemm_awt(const float* __restrict__ A, const float* __restrict__ W,
         float* __restrict__ C, const float* __restrict__ bias,
         int Nout, int K)
{
    gemm_core(A, W, C, bias, EPI, Nout, K, blockIdx.y * BM, blockIdx.x * BN);
}

// Fused 4-way projection: blockIdx.z selects {k, v, q, beta}.
struct ProjPtrs {
    const float* W[4];
    float*       C[4];
};

__global__ void __launch_bounds__(256, 2)
gemm_proj4(const float* __restrict__ A, ProjPtrs p, const float* __restrict__ bias,
           int Nout, int K)
{
    const int z = blockIdx.z;
    gemm_core(A, p.W[z], p.C[z], bias, (z == 3) ? 2 : 0, Nout, K,
              blockIdx.y * BM, blockIdx.x * BN);
}

// ---------------------------------------------------------------------------
// Barrier-free sequential scan. One WARP per (chain, state-row).
// 64 chains x 32 rows = 2048 warps. lane = state column j.
// State S[i][j] lives in one register per lane. All per-chain vector data
// (k, q) is loaded redundantly per warp (L1 broadcast); the k-norm reduction
// is recomputed per warp (deterministic) to avoid any inter-warp sync.
// ---------------------------------------------------------------------------
__global__ void __launch_bounds__(256)
scan_kernel(const float* __restrict__ Kp, const float* __restrict__ Vp,
            const float* __restrict__ Qp, const float* __restrict__ Bp,
            float* __restrict__ cell, float* __restrict__ S_final, int writeS)
{
    const int g     = blockIdx.x * 8 + (threadIdx.x >> 5);  // global warp id
    const int chain = g >> 5;          // 0..63  (b*H + h)
    const int i     = g & 31;          // state row
    const int j     = threadIdx.x & 31;// state col (lane)
    const int b     = chain >> 3;
    const int h     = chain & 7;

    float S = 0.f;
    size_t base = ((size_t)b * TT) * HN + (size_t)h * NN;

    // prefetch t = 0
    float kj = Kp[base + j];
    float qj = Qp[base + j];
    float vi = Vp[base + i];
    float bi = Bp[base + i];

    for (int t = 0; t < TT; ++t) {
        // issue next-step loads early (clamped on last step)
        const size_t nbase = (t + 1 < TT) ? base + HN : base;
        const float nk = Kp[nbase + j];
        const float nq = Qp[nbase + j];
        const float nv = Vp[nbase + i];
        const float nb = Bp[nbase + i];

        // dual interleaved butterfly reductions: ||k||^2 and S·k
        float s2 = kj * kj;
        float u  = S * kj;
#pragma unroll
        for (int o = 16; o > 0; o >>= 1) {
            s2 += __shfl_xor_sync(0xffffffffu, s2, o);
            u  += __shfl_xor_sync(0xffffffffu, u,  o);
        }
        const float inv = 1.f / (sqrtf(s2) + 1e-6f);
        const float knj = kj * inv;
        const float r   = u * inv;

        // state update
        S = tanhf(fmaf(bi, S, (vi - r) * knj));

        // Sq reduction
        float sq = S * qj;
#pragma unroll
        for (int o = 16; o > 0; o >>= 1)
            sq += __shfl_xor_sync(0xffffffffu, sq, o);

        if (j == 0) {
            // out = Sq * silu(Sq) = Sq^2 * sigmoid(Sq)
            cell[base + i] = sq * sq / (1.f + expf(-sq));
        }

        kj = nk; qj = nq; vi = nv; bi = nb;
        base += HN;
    }

    if (writeS) {
        S_final[((size_t)chain * NN + i) * NN + j] = S;
    }
}

// ---------------------------------------------------------------------------
// Host launcher
// ---------------------------------------------------------------------------
extern "C" void kernel_launch(void* const* d_in, const int* in_sizes, int n_in,
                              void* d_out, int out_size)
{
    const float* x      = (const float*)d_in[0];
    const float* W_in   = (const float*)d_in[1];
    const float* W_k    = (const float*)d_in[2];
    const float* W_v    = (const float*)d_in[3];
    const float* W_q    = (const float*)d_in[4];
    const float* W_beta = (const float*)d_in[5];
    const float* b_beta = (const float*)d_in[6];
    const float* W_out  = (const float*)d_in[7];
    float* y = (float*)d_out;

    float *xp, *k, *v, *q, *bt, *cell;
    cudaGetSymbolAddress((void**)&xp,   g_xp);
    cudaGetSymbolAddress((void**)&k,    g_k);
    cudaGetSymbolAddress((void**)&v,    g_v);
    cudaGetSymbolAddress((void**)&q,    g_q);
    cudaGetSymbolAddress((void**)&bt,   g_beta);
    cudaGetSymbolAddress((void**)&cell, g_cell);

    const int M = MROWS;

    // 1. xp = silu(x @ W_in^T)           [16384,1024] x [1024,1024]^T
    gemm_awt<1><<<dim3(DD / BN, M / BM), 256>>>(x, W_in, xp, nullptr, DD, DD);

    // 2. fused projections                [16384,256] = xp @ W^T  (x4)
    ProjPtrs p;
    p.W[0] = W_k;  p.W[1] = W_v;  p.W[2] = W_q;  p.W[3] = W_beta;
    p.C[0] = k;    p.C[1] = v;    p.C[2] = q;    p.C[3] = bt;
    gemm_proj4<<<dim3(HN / BN, M / BM, 4), 256>>>(xp, p, b_beta, HN, DD);

    // 3. sequential scan over T (barrier-free, warp-per-row)
    const size_t y_elems = (size_t)M * DD;
    const int writeS = (out_size >= (int)(y_elems + (size_t)BB * HH * NN * NN)) ? 1 : 0;
    scan_kernel<<<256, 256>>>(k, v, q, bt, cell, y + y_elems, writeS);

    // 4. y = cell @ W_out^T               [16384,1024] = [16384,256] x [1024,256]^T
    gemm_awt<0><<<dim3(DD / BN, M / BM), 256>>>(cell, W_out, y, nullptr, DD, HN);
}

// round 3
// speedup vs baseline: 1.6373x; 1.1725x over previous
#include <cuda_runtime.h>
#include <cstddef>

// Problem constants
#define BB 8
#define TT 2048
#define DD 1024
#define HH 8
#define NN 32
#define MROWS (BB*TT)          // 16384
#define HN (HH*NN)             // 256

// ---------------------------------------------------------------------------
// Scratch (no cudaMalloc allowed) — __device__ globals.
// ---------------------------------------------------------------------------
__device__ float g_xp  [(size_t)MROWS * DD];   // 64 MB
__device__ float g_k   [(size_t)MROWS * HN];   // 16 MB
__device__ float g_v   [(size_t)MROWS * HN];
__device__ float g_q   [(size_t)MROWS * HN];
__device__ float g_beta[(size_t)MROWS * HN];
__device__ float g_cell[(size_t)MROWS * HN];

// ---------------------------------------------------------------------------
// Shared double-buffered SGEMM core (unchanged from round 2).
// C[M,Nout] = epi( A[M,K] @ W[Nout,K]^T )   row-major fp32
// epi: 0 identity, 1 silu, 2 sigmoid(acc + bias[col])
// ---------------------------------------------------------------------------
#define BM 128
#define BN 128
#define BK 8
#define TM 8
#define TN 8

__device__ __forceinline__ void gemm_core(
    const float* __restrict__ A, const float* __restrict__ W,
    float* __restrict__ C, const float* __restrict__ bias,
    int epi, int Nout, int K, int row0, int col0)
{
    __shared__ float As[2][BK][BM];
    __shared__ float Bs[2][BK][BN];

    const int tid = threadIdx.x;
    const int lr = tid >> 1;            // 0..127
    const int lc = (tid & 1) << 2;      // 0 or 4

    const float* Ap = A + (size_t)(row0 + lr) * K + lc;
    const float* Wp = W + (size_t)(col0 + lr) * K + lc;

    const int ty = (tid >> 4) * TM;     // 0..120
    const int tx = (tid & 15) * TN;     // 0..120

    float acc[TM][TN];
#pragma unroll
    for (int m = 0; m < TM; ++m)
#pragma unroll
        for (int n = 0; n < TN; ++n) acc[m][n] = 0.f;

    const int ntiles = K / BK;

    float4 av = *reinterpret_cast<const float4*>(Ap);
    float4 wv = *reinterpret_cast<const float4*>(Wp);
    As[0][lc + 0][lr] = av.x; As[0][lc + 1][lr] = av.y;
    As[0][lc + 2][lr] = av.z; As[0][lc + 3][lr] = av.w;
    Bs[0][lc + 0][lr] = wv.x; Bs[0][lc + 1][lr] = wv.y;
    Bs[0][lc + 2][lr] = wv.z; Bs[0][lc + 3][lr] = wv.w;
    __syncthreads();

    for (int kt = 0; kt < ntiles; ++kt) {
        const int cur = kt & 1;
        if (kt + 1 < ntiles) {
            av = *reinterpret_cast<const float4*>(Ap + (size_t)(kt + 1) * BK);
            wv = *reinterpret_cast<const float4*>(Wp + (size_t)(kt + 1) * BK);
        }
#pragma unroll
        for (int kk = 0; kk < BK; ++kk) {
            float4 a0 = *reinterpret_cast<const float4*>(&As[cur][kk][ty]);
            float4 a1 = *reinterpret_cast<const float4*>(&As[cur][kk][ty + 4]);
            float4 b0 = *reinterpret_cast<const float4*>(&Bs[cur][kk][tx]);
            float4 b1 = *reinterpret_cast<const float4*>(&Bs[cur][kk][tx + 4]);
            float a[TM] = {a0.x, a0.y, a0.z, a0.w, a1.x, a1.y, a1.z, a1.w};
            float bb[TN] = {b0.x, b0.y, b0.z, b0.w, b1.x, b1.y, b1.z, b1.w};
#pragma unroll
            for (int m = 0; m < TM; ++m)
#pragma unroll
                for (int n = 0; n < TN; ++n)
                    acc[m][n] = fmaf(a[m], bb[n], acc[m][n]);
        }
        if (kt + 1 < ntiles) {
            const int nxt = cur ^ 1;
            As[nxt][lc + 0][lr] = av.x; As[nxt][lc + 1][lr] = av.y;
            As[nxt][lc + 2][lr] = av.z; As[nxt][lc + 3][lr] = av.w;
            Bs[nxt][lc + 0][lr] = wv.x; Bs[nxt][lc + 1][lr] = wv.y;
            Bs[nxt][lc + 2][lr] = wv.z; Bs[nxt][lc + 3][lr] = wv.w;
            __syncthreads();
        }
    }

#pragma unroll
    for (int m = 0; m < TM; ++m) {
        float* crow = C + (size_t)(row0 + ty + m) * Nout + col0 + tx;
#pragma unroll
        for (int n = 0; n < TN; ++n) {
            float v = acc[m][n];
            if (epi == 1) {
                v = v / (1.f + expf(-v));                       // silu
            } else if (epi == 2) {
                v = 1.f / (1.f + expf(-(v + bias[col0 + tx + n])));  // sigmoid+bias
            }
            crow[n] = v;
        }
    }
}

template<int EPI>
__global__ void __launch_bounds__(256, 2)
gemm_awt(const float* __restrict__ A, const float* __restrict__ W,
         float* __restrict__ C, const float* __restrict__ bias,
         int Nout, int K)
{
    gemm_core(A, W, C, bias, EPI, Nout, K, blockIdx.y * BM, blockIdx.x * BN);
}

struct ProjPtrs {
    const float* W[4];
    float*       C[4];
};

__global__ void __launch_bounds__(256, 2)
gemm_proj4(const float* __restrict__ A, ProjPtrs p, const float* __restrict__ bias,
           int Nout, int K)
{
    const int z = blockIdx.z;
    gemm_core(A, p.W[z], p.C[z], bias, (z == 3) ? 2 : 0, Nout, K,
              blockIdx.y * BM, blockIdx.x * BN);
}

// ---------------------------------------------------------------------------
// k-normalization (in place): kn = k / (||k|| + 1e-6), one warp per 32-vector.
// Layout: g_k[(b*T + t)*HN + h*NN + j]  ->  rows of 32 are contiguous.
// ---------------------------------------------------------------------------
__global__ void __launch_bounds__(256)
knorm_kernel(float* __restrict__ kk)
{
    const size_t r = (size_t)blockIdx.x * 8 + (threadIdx.x >> 5);
    const int j = threadIdx.x & 31;
    const size_t a = r * 32 + j;
    const float v = kk[a];
    float s2 = v * v;
#pragma unroll
    for (int o = 16; o > 0; o >>= 1) s2 += __shfl_xor_sync(0xffffffffu, s2, o);
    kk[a] = v / (sqrtf(s2) + 1e-6f);
}

// ---------------------------------------------------------------------------
// Barrier-free sequential scan, one WARP per (chain, state-row), lane = column.
//  * k is pre-normalized -> no norm reduction on the critical path
//  * register prefetch ring of depth 4 -> DRAM latency (577cyc) covered
//  * Sq (output) reduction deferred one step, interleaved with the S·kn
//    reduction of the next step -> off the critical path
//  * tanh(z) = 1 - 2/(exp(2z)+1) via __expf (~1e-7 abs err)
// ---------------------------------------------------------------------------
#define PF 4

__global__ void __launch_bounds__(256)
scan_kernel(const float* __restrict__ Kn, const float* __restrict__ Vp,
            const float* __restrict__ Qp, const float* __restrict__ Bp,
            float* __restrict__ cell, float* __restrict__ S_final, int writeS)
{
    const int g     = blockIdx.x * 8 + (threadIdx.x >> 5);  // global warp id
    const int chain = g >> 5;          // 0..63
    const int i     = g & 31;          // state row
    const int j     = threadIdx.x & 31;// state col
    const size_t cb = ((size_t)(chain >> 3) * TT) * HN + (size_t)(chain & 7) * NN;

    float pk[PF], pq[PF], pv[PF], pb[PF];
#pragma unroll
    for (int d = 0; d < PF; ++d) {
        const size_t a = cb + (size_t)d * HN;
        pk[d] = Kn[a + j]; pq[d] = Qp[a + j];
        pv[d] = Vp[a + i]; pb[d] = Bp[a + i];
    }

    float S = 0.f, sqp = 0.f;      // sqp: pending S·q partial from prev step
    size_t base = cb;              // row address of current step t

    for (int t = 0; t < TT; t += PF) {
#pragma unroll
        for (int u = 0; u < PF; ++u) {
            const int tcur = t + u;
            const int tpre = (tcur + PF < TT) ? (tcur + PF) : (TT - 1);
            const size_t pa = cb + (size_t)tpre * HN;
            const float nk = Kn[pa + j];
            const float nq = Qp[pa + j];
            const float nv = Vp[pa + i];
            const float nb = Bp[pa + i];

            // dual interleaved butterflies: current S·kn, previous S·q
            float uu = S * pk[u];
            float sv = sqp;
#pragma unroll
            for (int o = 16; o > 0; o >>= 1) {
                uu += __shfl_xor_sync(0xffffffffu, uu, o);
                sv += __shfl_xor_sync(0xffffffffu, sv, o);
            }
            // lazy store of previous step's output: out = sv^2 * sigmoid(sv)
            if (tcur > 0 && j == 0)
                cell[base - HN + i] = sv * sv / (1.f + __expf(-sv));

            // state update: S = tanh(beta_i*S + (v_i - S·kn)*kn_j)
            const float z = fmaf(pb[u], S, (pv[u] - uu) * pk[u]);
            const float e = __expf(2.f * z);
            S = 1.f - 2.f / (e + 1.f);
            sqp = S * pq[u];

            pk[u] = nk; pq[u] = nq; pv[u] = nv; pb[u] = nb;
            base += HN;
        }
    }

    // final step's output
    float sv = sqp;
#pragma unroll
    for (int o = 16; o > 0; o >>= 1) sv += __shfl_xor_sync(0xffffffffu, sv, o);
    if (j == 0)
        cell[base - HN + i] = sv * sv / (1.f + __expf(-sv));

    if (writeS)
        S_final[((size_t)chain * NN + i) * NN + j] = S;
}

// ---------------------------------------------------------------------------
// Host launcher
// ---------------------------------------------------------------------------
extern "C" void kernel_launch(void* const* d_in, const int* in_sizes, int n_in,
                              void* d_out, int out_size)
{
    const float* x      = (const float*)d_in[0];
    const float* W_in   = (const float*)d_in[1];
    const float* W_k    = (const float*)d_in[2];
    const float* W_v    = (const float*)d_in[3];
    const float* W_q    = (const float*)d_in[4];
    const float* W_beta = (const float*)d_in[5];
    const float* b_beta = (const float*)d_in[6];
    const float* W_out  = (const float*)d_in[7];
    float* y = (float*)d_out;

    float *xp, *k, *v, *q, *bt, *cell;
    cudaGetSymbolAddress((void**)&xp,   g_xp);
    cudaGetSymbolAddress((void**)&k,    g_k);
    cudaGetSymbolAddress((void**)&v,    g_v);
    cudaGetSymbolAddress((void**)&q,    g_q);
    cudaGetSymbolAddress((void**)&bt,   g_beta);
    cudaGetSymbolAddress((void**)&cell, g_cell);

    const int M = MROWS;

    // 1. xp = silu(x @ W_in^T)
    gemm_awt<1><<<dim3(DD / BN, M / BM), 256>>>(x, W_in, xp, nullptr, DD, DD);

    // 2. fused projections (k, v, q, beta)
    ProjPtrs p;
    p.W[0] = W_k;  p.W[1] = W_v;  p.W[2] = W_q;  p.W[3] = W_beta;
    p.C[0] = k;    p.C[1] = v;    p.C[2] = q;    p.C[3] = bt;
    gemm_proj4<<<dim3(HN / BN, M / BM, 4), 256>>>(xp, p, b_beta, HN, DD);

    // 3. normalize k in place (one warp per 32-vector)
    knorm_kernel<<<(MROWS * HH) / 8, 256>>>(k);

    // 4. sequential scan
    const size_t y_elems = (size_t)M * DD;
    const int writeS = (out_size >= (int)(y_elems + (size_t)BB * HH * NN * NN)) ? 1 : 0;
    scan_kernel<<<256, 256>>>(k, v, q, bt, cell, y + y_elems, writeS);

    // 5. y = cell @ W_out^T
    gemm_awt<0><<<dim3(DD / BN, M / BM), 256>>>(cell, W_out, y, nullptr, DD, HN);
}

// round 5
// speedup vs baseline: 3.0961x; 1.8910x over previous
#include <cuda_runtime.h>
#include <cstddef>
#include <cstdint>

// Problem constants
#define BB 8
#define TT 2048
#define DD 1024
#define HH 8
#define NN 32
#define MROWS (BB*TT)          // 16384
#define HN (HH*NN)             // 256

// ---------------------------------------------------------------------------
// Scratch (no cudaMalloc allowed) — __device__ globals.
// ---------------------------------------------------------------------------
__device__ float g_xp  [(size_t)MROWS * DD];   // 64 MB
__device__ float g_k   [(size_t)MROWS * HN];   // 16 MB
__device__ float g_v   [(size_t)MROWS * HN];
__device__ float g_q   [(size_t)MROWS * HN];
__device__ float g_beta[(size_t)MROWS * HN];
__device__ float g_cell[(size_t)MROWS * HN];

// ---------------------------------------------------------------------------
// tf32 helpers
// ---------------------------------------------------------------------------
__device__ __forceinline__ unsigned f2tf32(float x) {
    unsigned u;
    asm("cvt.rna.tf32.f32 %0, %1;" : "=r"(u) : "f"(x));
    return u;
}

__device__ __forceinline__ void mma_tf32(float d[4],
                                         unsigned a0, unsigned a1,
                                         unsigned a2, unsigned a3,
                                         unsigned b0, unsigned b1) {
    asm("mma.sync.aligned.m16n8k8.row.col.f32.tf32.tf32.f32 "
        "{%0,%1,%2,%3}, {%4,%5,%6,%7}, {%8,%9}, {%0,%1,%2,%3};"
        : "+f"(d[0]), "+f"(d[1]), "+f"(d[2]), "+f"(d[3])
        : "r"(a0), "r"(a1), "r"(a2), "r"(a3), "r"(b0), "r"(b1));
}

// ---------------------------------------------------------------------------
// tf32 tensor-core GEMM: C[M,Nout] = epi( A[M,K] @ W[Nout,K]^T )
// Block tile 128x128, BK=16, 8 warps (2 along M x 4 along N), warp tile 64x32.
// Per k8 sub-chunk: 4 A-fragments (m16) x 4 B-fragments (n8) -> 16 mma.
// epi: 0 identity, 1 silu, 2 sigmoid(acc + bias[col])
// ---------------------------------------------------------------------------
#define SSTR 20    // smem row stride in 32-bit words (conflict-free for frags)

__device__ __forceinline__ void mma_gemm_core(
    const float* __restrict__ A, const float* __restrict__ W,
    float* __restrict__ C, const float* __restrict__ bias,
    int epi, int Nout, int K, int row0, int col0)
{
    __shared__ unsigned As[2][128 * SSTR];
    __shared__ unsigned Ws[2][128 * SSTR];

    const int tid  = threadIdx.x;
    const int wid  = tid >> 5;
    const int lane = tid & 31;
    const int g    = lane >> 2;     // fragment group row 0..7
    const int c    = lane & 3;      // fragment k-col 0..3
    const int wm   = (wid & 1) * 64;   // warp row offset in tile
    const int wn   = (wid >> 1) * 32;  // warp col offset in tile

    // Global staging: each thread loads 8 floats (2 x float4) per operand tile.
    // row = tid>>1 (0..127), col = (tid&1)*8  (+0 and +4 within)
    const int lr = tid >> 1;
    const int lc = (tid & 1) * 8;
    const float* Ap = A + (size_t)(row0 + lr) * K + lc;
    const float* Wp = W + (size_t)(col0 + lr) * K + lc;
    unsigned* AsRow0 = &As[0][lr * SSTR + lc];
    unsigned* WsRow0 = &Ws[0][lr * SSTR + lc];
    unsigned* AsRow1 = &As[1][lr * SSTR + lc];
    unsigned* WsRow1 = &Ws[1][lr * SSTR + lc];

    float acc[4][4][4];
#pragma unroll
    for (int mt = 0; mt < 4; ++mt)
#pragma unroll
        for (int nt = 0; nt < 4; ++nt)
#pragma unroll
            for (int e = 0; e < 4; ++e) acc[mt][nt][e] = 0.f;

    const int nchunks = K / 16;

    // prologue: stage chunk 0 into buffer 0
    {
        float4 aa = *reinterpret_cast<const float4*>(Ap);
        float4 ab = *reinterpret_cast<const float4*>(Ap + 4);
        float4 wa = *reinterpret_cast<const float4*>(Wp);
        float4 wb = *reinterpret_cast<const float4*>(Wp + 4);
        AsRow0[0] = f2tf32(aa.x); AsRow0[1] = f2tf32(aa.y);
        AsRow0[2] = f2tf32(aa.z); AsRow0[3] = f2tf32(aa.w);
        AsRow0[4] = f2tf32(ab.x); AsRow0[5] = f2tf32(ab.y);
        AsRow0[6] = f2tf32(ab.z); AsRow0[7] = f2tf32(ab.w);
        WsRow0[0] = f2tf32(wa.x); WsRow0[1] = f2tf32(wa.y);
        WsRow0[2] = f2tf32(wa.z); WsRow0[3] = f2tf32(wa.w);
        WsRow0[4] = f2tf32(wb.x); WsRow0[5] = f2tf32(wb.y);
        WsRow0[6] = f2tf32(wb.z); WsRow0[7] = f2tf32(wb.w);
    }
    __syncthreads();

    for (int chunk = 0; chunk < nchunks; ++chunk) {
        const int cur = chunk & 1;
        float4 aa, ab, wa, wb;
        const bool more = (chunk + 1 < nchunks);
        if (more) {
            const int ko = (chunk + 1) * 16;
            aa = *reinterpret_cast<const float4*>(Ap + ko);
            ab = *reinterpret_cast<const float4*>(Ap + ko + 4);
            wa = *reinterpret_cast<const float4*>(Wp + ko);
            wb = *reinterpret_cast<const float4*>(Wp + ko + 4);
        }

        const unsigned* Ab = As[cur];
        const unsigned* Wb = Ws[cur];
#pragma unroll
        for (int kk = 0; kk < 2; ++kk) {
            unsigned af[4][4];
#pragma unroll
            for (int mt = 0; mt < 4; ++mt) {
                const int rb = wm + mt * 16;
                const unsigned* p0 = &Ab[(rb + g)     * SSTR + kk * 8 + c];
                const unsigned* p1 = &Ab[(rb + 8 + g) * SSTR + kk * 8 + c];
                af[mt][0] = p0[0];
                af[mt][1] = p1[0];
                af[mt][2] = p0[4];
                af[mt][3] = p1[4];
            }
#pragma unroll
            for (int nt = 0; nt < 4; ++nt) {
                const unsigned* pb = &Wb[(wn + nt * 8 + g) * SSTR + kk * 8 + c];
                const unsigned b0 = pb[0];
                const unsigned b1 = pb[4];
#pragma unroll
                for (int mt = 0; mt < 4; ++mt)
                    mma_tf32(acc[mt][nt], af[mt][0], af[mt][1], af[mt][2], af[mt][3], b0, b1);
            }
        }

        if (more) {
            unsigned* ad = (cur ? AsRow0 : AsRow1);
            unsigned* wd = (cur ? WsRow0 : WsRow1);
            ad[0] = f2tf32(aa.x); ad[1] = f2tf32(aa.y);
            ad[2] = f2tf32(aa.z); ad[3] = f2tf32(aa.w);
            ad[4] = f2tf32(ab.x); ad[5] = f2tf32(ab.y);
            ad[6] = f2tf32(ab.z); ad[7] = f2tf32(ab.w);
            wd[0] = f2tf32(wa.x); wd[1] = f2tf32(wa.y);
            wd[2] = f2tf32(wa.z); wd[3] = f2tf32(wa.w);
            wd[4] = f2tf32(wb.x); wd[5] = f2tf32(wb.y);
            wd[6] = f2tf32(wb.z); wd[7] = f2tf32(wb.w);
        }
        __syncthreads();
    }

    // Epilogue: thread owns (row=g(+8), col=2c(+1)) of each 16x8 sub-tile.
#pragma unroll
    for (int mt = 0; mt < 4; ++mt) {
        const int r0 = row0 + wm + mt * 16 + g;
#pragma unroll
        for (int nt = 0; nt < 4; ++nt) {
            const int cc = col0 + wn + nt * 8 + 2 * c;
            float d0 = acc[mt][nt][0], d1 = acc[mt][nt][1];
            float d2 = acc[mt][nt][2], d3 = acc[mt][nt][3];
            if (epi == 1) {
                d0 = d0 / (1.f + __expf(-d0));
                d1 = d1 / (1.f + __expf(-d1));
                d2 = d2 / (1.f + __expf(-d2));
                d3 = d3 / (1.f + __expf(-d3));
            } else if (epi == 2) {
                const float b0 = bias[cc], b1 = bias[cc + 1];
                d0 = 1.f / (1.f + __expf(-(d0 + b0)));
                d1 = 1.f / (1.f + __expf(-(d1 + b1)));
                d2 = 1.f / (1.f + __expf(-(d2 + b0)));
                d3 = 1.f / (1.f + __expf(-(d3 + b1)));
            }
            *reinterpret_cast<float2*>(C + (size_t)r0 * Nout + cc)       = make_float2(d0, d1);
            *reinterpret_cast<float2*>(C + (size_t)(r0 + 8) * Nout + cc) = make_float2(d2, d3);
        }
    }
}

template<int EPI>
__global__ void __launch_bounds__(256, 2)
gemm_awt(const float* __restrict__ A, const float* __restrict__ W,
         float* __restrict__ C, const float* __restrict__ bias,
         int Nout, int K)
{
    mma_gemm_core(A, W, C, bias, EPI, Nout, K, blockIdx.y * 128, blockIdx.x * 128);
}

struct ProjPtrs {
    const float* W[4];
    float*       C[4];
};

__global__ void __launch_bounds__(256, 2)
gemm_proj4(const float* __restrict__ A, ProjPtrs p, const float* __restrict__ bias,
           int Nout, int K)
{
    const int z = blockIdx.z;
    mma_gemm_core(A, p.W[z], p.C[z], bias, (z == 3) ? 2 : 0, Nout, K,
                  blockIdx.y * 128, blockIdx.x * 128);
}

// ---------------------------------------------------------------------------
// k-normalization (in place): kn = k / (||k|| + 1e-6), one warp per 32-vector.
// ---------------------------------------------------------------------------
__global__ void __launch_bounds__(256)
knorm_kernel(float* __restrict__ kk)
{
    const size_t r = (size_t)blockIdx.x * 8 + (threadIdx.x >> 5);
    const int j = threadIdx.x & 31;
    const size_t a = r * 32 + j;
    const float v = kk[a];
    float s2 = v * v;
#pragma unroll
    for (int o = 16; o > 0; o >>= 1) s2 += __shfl_xor_sync(0xffffffffu, s2, o);
    kk[a] = v / (sqrtf(s2) + 1e-6f);
}

// ---------------------------------------------------------------------------
// Barrier-free sequential scan (round-3 proven version): one WARP per
// (chain, state-row), lane = column. k pre-normalized, prefetch ring depth 4,
// dual interleaved shfl butterflies (current S·kn + previous S·q),
// tanh via __expf.
// ---------------------------------------------------------------------------
#define PF 4

__global__ void __launch_bounds__(256)
scan_kernel(const float* __restrict__ Kn, const float* __restrict__ Vp,
            const float* __restrict__ Qp, const float* __restrict__ Bp,
            float* __restrict__ cell, float* __restrict__ S_final, int writeS)
{
    const int g     = blockIdx.x * 8 + (threadIdx.x >> 5);  // global warp id
    const int chain = g >> 5;          // 0..63
    const int i     = g & 31;          // state row
    const int j     = threadIdx.x & 31;// state col
    const size_t cb = ((size_t)(chain >> 3) * TT) * HN + (size_t)(chain & 7) * NN;

    float pk[PF], pq[PF], pv[PF], pb[PF];
#pragma unroll
    for (int d = 0; d < PF; ++d) {
        const size_t a = cb + (size_t)d * HN;
        pk[d] = Kn[a + j]; pq[d] = Qp[a + j];
        pv[d] = Vp[a + i]; pb[d] = Bp[a + i];
    }

    float S = 0.f, sqp = 0.f;      // sqp: pending S·q partial from prev step
    size_t base = cb;

    for (int t = 0; t < TT; t += PF) {
#pragma unroll
        for (int u = 0; u < PF; ++u) {
            const int tcur = t + u;
            const int tpre = (tcur + PF < TT) ? (tcur + PF) : (TT - 1);
            const size_t pa = cb + (size_t)tpre * HN;
            const float nk = Kn[pa + j];
            const float nq = Qp[pa + j];
            const float nv = Vp[pa + i];
            const float nb = Bp[pa + i];

            // dual interleaved butterflies: current S·kn, previous S·q
            float uu = S * pk[u];
            float sv = sqp;
#pragma unroll
            for (int o = 16; o > 0; o >>= 1) {
                uu += __shfl_xor_sync(0xffffffffu, uu, o);
                sv += __shfl_xor_sync(0xffffffffu, sv, o);
            }
            // lazy store of previous step's output
            if (tcur > 0 && j == 0)
                cell[base - HN + i] = sv * sv / (1.f + __expf(-sv));

            // state update: S = tanh(beta_i*S + (v_i - S·kn)*kn_j)
            const float z = fmaf(pb[u], S, (pv[u] - uu) * pk[u]);
            const float e = __expf(2.f * z);
            S = 1.f - 2.f / (e + 1.f);
            sqp = S * pq[u];

            pk[u] = nk; pq[u] = nq; pv[u] = nv; pb[u] = nb;
            base += HN;
        }
    }

    float sv = sqp;
#pragma unroll
    for (int o = 16; o > 0; o >>= 1) sv += __shfl_xor_sync(0xffffffffu, sv, o);
    if (j == 0)
        cell[base - HN + i] = sv * sv / (1.f + __expf(-sv));

    if (writeS)
        S_final[((size_t)chain * NN + i) * NN + j] = S;
}

// ---------------------------------------------------------------------------
// Host launcher
// ---------------------------------------------------------------------------
extern "C" void kernel_launch(void* const* d_in, const int* in_sizes, int n_in,
                              void* d_out, int out_size)
{
    const float* x      = (const float*)d_in[0];
    const float* W_in   = (const float*)d_in[1];
    const float* W_k    = (const float*)d_in[2];
    const float* W_v    = (const float*)d_in[3];
    const float* W_q    = (const float*)d_in[4];
    const float* W_beta = (const float*)d_in[5];
    const float* b_beta = (const float*)d_in[6];
    const float* W_out  = (const float*)d_in[7];
    float* y = (float*)d_out;

    float *xp, *k, *v, *q, *bt, *cell;
    cudaGetSymbolAddress((void**)&xp,   g_xp);
    cudaGetSymbolAddress((void**)&k,    g_k);
    cudaGetSymbolAddress((void**)&v,    g_v);
    cudaGetSymbolAddress((void**)&q,    g_q);
    cudaGetSymbolAddress((void**)&bt,   g_beta);
    cudaGetSymbolAddress((void**)&cell, g_cell);

    const int M = MROWS;

    // 1. xp = silu(x @ W_in^T)     [16384,1024] = [16384,1024] x [1024,1024]^T
    gemm_awt<1><<<dim3(DD / 128, M / 128), 256>>>(x, W_in, xp, nullptr, DD, DD);

    // 2. fused projections (k, v, q, beta)   [16384,256] each
    ProjPtrs p;
    p.W[0] = W_k;  p.W[1] = W_v;  p.W[2] = W_q;  p.W[3] = W_beta;
    p.C[0] = k;    p.C[1] = v;    p.C[2] = q;    p.C[3] = bt;
    gemm_proj4<<<dim3(HN / 128, M / 128, 4), 256>>>(xp, p, b_beta, HN, DD);

    // 3. normalize k in place
    knorm_kernel<<<(MROWS * HH) / 8, 256>>>(k);

    // 4. sequential scan
    const size_t y_elems = (size_t)M * DD;
    const int writeS = (out_size >= (int)(y_elems + (size_t)BB * HH * NN * NN)) ? 1 : 0;
    scan_kernel<<<256, 256>>>(k, v, q, bt, cell, y + y_elems, writeS);

    // 5. y = cell @ W_out^T        [16384,1024] = [16384,256] x [1024,256]^T
    gemm_awt<0><<<dim3(DD / 128, M / 128), 256>>>(cell, W_out, y, nullptr, DD, HN);
}